// round 6
// baseline (speedup 1.0000x reference)
#include <cuda_runtime.h>

// out[n, f, h] = x[n, f] * W[f, h] + b[f, h]
// BATCH=16384, F=128, H=64, fp32. 512 MiB output -> streaming-store bound.
//
// R4: Blackwell 256-bit stores (st.global.v8.f32). Each thread owns one
// (f, h8) octet: loads 8 W + 8 b floats once, then for 8 batch rows does
// 1 broadcast x load + 1 STG.256. Per warp-store: 1024 B contiguous.
// Plain stores (no .cs) to test evict-policy interaction.

#define BATCH 16384
#define NFEAT 128
#define HID   64
#define H8    (HID / 8)                // 8 octets per feature
#define FH8   (NFEAT * H8)             // 1024 (f,h8) units
#define TPB   256
#define FH8_BLOCKS (FH8 / TPB)         // 4
#define N_PER_THREAD 8
#define N_CHUNKS (BATCH / N_PER_THREAD) // 2048

__global__ __launch_bounds__(TPB)
void ifll_kernel(const float* __restrict__ x,
                 const float4* __restrict__ W4,
                 const float4* __restrict__ b4,
                 float* __restrict__ out)
{
    // blockIdx.x = n_chunk * FH8_BLOCKS + f_block
    int fh8 = (blockIdx.x & (FH8_BLOCKS - 1)) * TPB + threadIdx.x; // 0..1023
    int n0  = (blockIdx.x >> 2) * N_PER_THREAD;

    int f = fh8 >> 3;                  // feature index (8 lanes share one f)

    // Per-thread invariant weights: 8 W + 8 b floats, loaded once.
    float4 w0 = __ldg(&W4[fh8 * 2 + 0]);
    float4 w1 = __ldg(&W4[fh8 * 2 + 1]);
    float4 c0 = __ldg(&b4[fh8 * 2 + 0]);
    float4 c1 = __ldg(&b4[fh8 * 2 + 1]);

    const float* xp = x + (size_t)n0 * NFEAT + f;
    float*       op = out + (size_t)n0 * (NFEAT * HID) + (size_t)fh8 * 8;

    // Front-batch the 8 independent x loads.
    float xv[N_PER_THREAD];
    #pragma unroll
    for (int i = 0; i < N_PER_THREAD; i++)
        xv[i] = __ldg(xp + i * NFEAT);

    // Pure 256-bit store stream: 1 STG.256 per row per thread.
    #pragma unroll
    for (int i = 0; i < N_PER_THREAD; i++) {
        float o0 = fmaf(xv[i], w0.x, c0.x);
        float o1 = fmaf(xv[i], w0.y, c0.y);
        float o2 = fmaf(xv[i], w0.z, c0.z);
        float o3 = fmaf(xv[i], w0.w, c0.w);
        float o4 = fmaf(xv[i], w1.x, c1.x);
        float o5 = fmaf(xv[i], w1.y, c1.y);
        float o6 = fmaf(xv[i], w1.z, c1.z);
        float o7 = fmaf(xv[i], w1.w, c1.w);
        float* p = op + (size_t)i * (NFEAT * HID);
        asm volatile(
            "st.global.v8.f32 [%0], {%1, %2, %3, %4, %5, %6, %7, %8};"
            :: "l"(p),
               "f"(o0), "f"(o1), "f"(o2), "f"(o3),
               "f"(o4), "f"(o5), "f"(o6), "f"(o7)
            : "memory");
    }
}

extern "C" void kernel_launch(void* const* d_in, const int* in_sizes, int n_in,
                              void* d_out, int out_size)
{
    const float*  x  = (const float*)d_in[0];
    const float4* W4 = (const float4*)d_in[1];
    const float4* b4 = (const float4*)d_in[2];
    float* out = (float*)d_out;

    const int blocks = N_CHUNKS * FH8_BLOCKS;  // 8192
    ifll_kernel<<<blocks, TPB>>>(x, W4, b4, out);
}

// round 10
// speedup vs baseline: 1.4282x; 1.4282x over previous
#include <cuda_runtime.h>

// out[n, f, h] = x[n, f] * W[f, h] + b[f, h]
// BATCH=16384, F=128, H=64, fp32. 512 MiB output -> streaming-store bound.
//
// R8 (= R6 resubmitted after infra failure): R2 structure (STG.128 + __stcs,
// thread owns (f,h4) x 16 rows) but x is staged through shared memory: one
// cooperative LDG.32 per thread loads the block's 16-row x 16-feature x-tile
// (1 KiB), then the inner loop reads x via broadcast LDS instead of 16 scalar
// LDGs. Removes ~16 L1tex global-path wavefronts per warp-chunk, leaving the
// global pipe to the store stream.

#define BATCH 16384
#define NFEAT 128
#define HID   64
#define H4    (HID / 4)               // 16
#define FH    (NFEAT * H4)            // 2048 (f,h4) pairs
#define TPB   256
#define FH_BLOCKS (FH / TPB)          // 8  (16 features per block)
#define N_PER_THREAD 16
#define N_CHUNKS (BATCH / N_PER_THREAD) // 1024

__global__ __launch_bounds__(TPB)
void ifll_kernel(const float* __restrict__ x,
                 const float4* __restrict__ W4,
                 const float4* __restrict__ b4,
                 float4* __restrict__ out)
{
    __shared__ float xs[N_PER_THREAD * 16];   // [n_local][f_local], 16x16

    // blockIdx.x = n_chunk * FH_BLOCKS + f_block
    int f_block = blockIdx.x & (FH_BLOCKS - 1);
    int fh = f_block * TPB + threadIdx.x;     // 0..2047
    int n0 = (blockIdx.x >> 3) * N_PER_THREAD;
    int f0 = f_block * 16;                    // first feature of this block

    // Cooperative x-tile load: thread t -> x[n0 + (t>>4), f0 + (t&15)].
    {
        int nl = threadIdx.x >> 4;
        int fl = threadIdx.x & 15;
        xs[threadIdx.x] = __ldg(&x[(size_t)(n0 + nl) * NFEAT + f0 + fl]);
    }

    // Per-thread invariant weights.
    float4 w  = __ldg(&W4[fh]);
    float4 bb = __ldg(&b4[fh]);

    __syncthreads();

    int f_local = (threadIdx.x >> 4);         // 0..15 within block, == f - f0
    float4* op = out + (size_t)n0 * FH + fh;

    #pragma unroll
    for (int i = 0; i < N_PER_THREAD; i++) {
        float xv = xs[i * 16 + f_local];      // broadcast LDS, conflict-free
        float4 o;
        o.x = fmaf(xv, w.x, bb.x);
        o.y = fmaf(xv, w.y, bb.y);
        o.z = fmaf(xv, w.z, bb.z);
        o.w = fmaf(xv, w.w, bb.w);
        __stcs(op + (size_t)i * FH, o);
    }
}

extern "C" void kernel_launch(void* const* d_in, const int* in_sizes, int n_in,
                              void* d_out, int out_size)
{
    const float*  x  = (const float*)d_in[0];
    const float4* W4 = (const float4*)d_in[1];
    const float4* b4 = (const float4*)d_in[2];
    float4* out = (float4*)d_out;

    const int blocks = N_CHUNKS * FH_BLOCKS;  // 8192
    ifll_kernel<<<blocks, TPB>>>(x, W4, b4, out);
}